// round 2
// baseline (speedup 1.0000x reference)
#include <cuda_runtime.h>
#include <math.h>

#define HWX 262144   // 512*512
#define KS  576      // 64 channels * 9 taps

// Scratch (no allocations allowed in kernel_launch)
__device__ unsigned g_actmax_bits[KS];
__device__ float    g_rk2[KS];     // 1 / (scale_k * s_qx)
__device__ float    g_sqx;         // fake-quant step for x

// ---------------------------------------------------------------------------
// Kernel 0: zero the act-max scratch (graph-capturable, deterministic)
// ---------------------------------------------------------------------------
__global__ void init_kernel() {
    int i = blockIdx.x * blockDim.x + threadIdx.x;
    if (i < KS) g_actmax_bits[i] = 0u;
}

// ---------------------------------------------------------------------------
// Kernel 1: per-channel windowed abs-max.
// Window (kh,kw) = all rows except {row511 if kh==0, row0 if kh==2},
//                  all cols except {col511 if kw==0, col0 if kw==2}.
// Interior elements feed all 9 windows -> fast path with a single running max.
// ---------------------------------------------------------------------------
__global__ __launch_bounds__(256) void actmax_kernel(const float* __restrict__ in) {
    int ch = blockIdx.y;
    const float4* p = reinterpret_cast<const float4*>(in + (size_t)ch * HWX);

    float m[9];
#pragma unroll
    for (int i = 0; i < 9; i++) m[i] = 0.f;
    float mi = 0.f;  // interior max (subset of every window)

    for (int i = blockIdx.x * blockDim.x + threadIdx.x; i < HWX / 4;
         i += gridDim.x * blockDim.x) {
        float4 v = p[i];
        float a0 = fabsf(v.x), a1 = fabsf(v.y), a2 = fabsf(v.z), a3 = fabsf(v.w);
        int e  = i << 2;
        int r  = e >> 9;
        int c0 = e & 511;
        if (r != 0 && r != 511 && c0 != 0 && c0 != 508) {
            mi = fmaxf(mi, fmaxf(fmaxf(a0, a1), fmaxf(a2, a3)));
        } else {
            bool r0 = (r != 511), r2 = (r != 0);
            float a[4] = {a0, a1, a2, a3};
#pragma unroll
            for (int j = 0; j < 4; j++) {
                int  c  = c0 + j;
                bool w0 = (c != 511), w2 = (c != 0);
                float av = a[j];
                m[0] = fmaxf(m[0], (r0 && w0) ? av : 0.f);
                m[1] = fmaxf(m[1],  r0        ? av : 0.f);
                m[2] = fmaxf(m[2], (r0 && w2) ? av : 0.f);
                m[3] = fmaxf(m[3],  w0        ? av : 0.f);
                m[4] = fmaxf(m[4],  av);
                m[5] = fmaxf(m[5],  w2        ? av : 0.f);
                m[6] = fmaxf(m[6], (r2 && w0) ? av : 0.f);
                m[7] = fmaxf(m[7],  r2        ? av : 0.f);
                m[8] = fmaxf(m[8], (r2 && w2) ? av : 0.f);
            }
        }
    }
#pragma unroll
    for (int i = 0; i < 9; i++) m[i] = fmaxf(m[i], mi);

    // warp reduce (values >= 0, so uint bit order == float order)
#pragma unroll
    for (int off = 16; off; off >>= 1) {
#pragma unroll
        for (int i = 0; i < 9; i++)
            m[i] = fmaxf(m[i], __shfl_xor_sync(0xffffffffu, m[i], off));
    }

    __shared__ unsigned sm[9];
    if (threadIdx.x < 9) sm[threadIdx.x] = 0u;
    __syncthreads();
    if ((threadIdx.x & 31) == 0) {
#pragma unroll
        for (int i = 0; i < 9; i++) atomicMax(&sm[i], __float_as_uint(m[i]));
    }
    __syncthreads();
    if (threadIdx.x < 9)
        atomicMax(&g_actmax_bits[ch * 9 + threadIdx.x], sm[threadIdx.x]);
}

// ---------------------------------------------------------------------------
// Kernel 2: scales, quant steps, and the wq output (tiny: one block).
//   scale_k = sqrt(act_k)/sqrt(wmax_k)  (==0 -> 1)
//   amax_x  = max_k act_k/scale_k ;  amax_w = max_k wmax_k*scale_k
//   wq[cout,kh,kw,c] = rint(clip(w*scale/s_qw)) * s_qw
// ---------------------------------------------------------------------------
__global__ __launch_bounds__(576) void scale_kernel(const float* __restrict__ w,
                                                    float* __restrict__ out) {
    __shared__ float red_ax[18], red_wx[18];
    __shared__ float s_q[2];

    int k = threadIdx.x;  // 0..575  (c,kh,kw) with k = c*9 + kh*3 + kw
    float act = __uint_as_float(g_actmax_bits[k]);
    float wm = 0.f;
    for (int co = 0; co < 64; ++co) wm = fmaxf(wm, fabsf(w[co * KS + k]));

    float sc = sqrtf(act) / sqrtf(wm);
    if (sc == 0.f) sc = 1.f;

    float ax = act / sc;   // per-column amax of x/scale
    float wx = wm * sc;    // per-column amax of w*scale

    // warp-level reduce then cross-warp
#pragma unroll
    for (int off = 16; off; off >>= 1) {
        ax = fmaxf(ax, __shfl_xor_sync(0xffffffffu, ax, off));
        wx = fmaxf(wx, __shfl_xor_sync(0xffffffffu, wx, off));
    }
    if ((k & 31) == 0) { red_ax[k >> 5] = ax; red_wx[k >> 5] = wx; }
    __syncthreads();
    if (k == 0) {
        float a = 0.f, b = 0.f;
        for (int i = 0; i < 18; i++) { a = fmaxf(a, red_ax[i]); b = fmaxf(b, red_wx[i]); }
        s_q[0] = (a > 0.f) ? a / 127.f : 1.f;   // s_qx
        s_q[1] = (b > 0.f) ? b / 127.f : 1.f;   // s_qw
        g_sqx  = s_q[0];
    }
    __syncthreads();
    float sqx = s_q[0], sqw = s_q[1];
    float rqw = 1.0f / sqw;

    g_rk2[k] = 1.0f / (sc * sqx);

    // wq output: layout (Cout, K, K, C) at the start of out
    int c  = k / 9, kh = (k % 9) / 3, kw = k % 3;
    int ob = kh * 192 + kw * 64 + c;
    for (int co = 0; co < 64; ++co) {
        float u = (w[co * KS + k] * sc) * rqw;
        u = fminf(fmaxf(u, -127.f), 127.f);
        out[co * KS + ob] = rintf(u) * sqw;
    }
}

// ---------------------------------------------------------------------------
// Kernel 3: fused 9-tap quantize-fold + NCHW->NHWC transpose.
// xf[h,w,c] = sum over valid taps of rint(v * rk2[c,t]) * s_qx
// Valid: kh=0 unless h==511; kh=2 unless h==0; kw symmetric in w.
// Block = one h row x 32 w x all 64 c; smem tile makes both sides coalesced.
// ---------------------------------------------------------------------------
__global__ __launch_bounds__(256) void main_kernel(const float* __restrict__ in,
                                                   float* __restrict__ out) {
    __shared__ float s_rk2[KS];
    __shared__ float tile[32][65];

    int tid = threadIdx.x;
    for (int i = tid; i < KS; i += 256) s_rk2[i] = g_rk2[i];
    float sq = g_sqx;

    int h  = blockIdx.y;
    int w0 = blockIdx.x * 32;
    int wl = tid & 31;
    int ww = w0 + wl;

    bool okh[3] = { h != 511, true, h != 0 };
    bool okw[3] = { ww != 511, true, ww != 0 };
    float msk[9];
#pragma unroll
    for (int kh = 0; kh < 3; kh++)
#pragma unroll
        for (int kw = 0; kw < 3; kw++)
            msk[kh * 3 + kw] = (okh[kh] && okw[kw]) ? sq : 0.f;

    __syncthreads();

    int cw = tid >> 5;                      // warp id: channel sub-index
    size_t inrow = (size_t)h * 512 + ww;
#pragma unroll
    for (int it = 0; it < 8; ++it) {
        int c = it * 8 + cw;
        float v = in[(size_t)c * HWX + inrow];
        const float* sp = &s_rk2[c * 9];
        float acc = 0.f;
#pragma unroll
        for (int t = 0; t < 9; t++) {
            float u = v * sp[t];            // == (v/scale)/s_qx up to ulps
            acc = fmaf(rintf(u), msk[t], acc);
        }
        tile[wl][c] = acc;
    }
    __syncthreads();

    float* ob = out + 36864 + ((size_t)h * 512 + (size_t)w0) * 64;
#pragma unroll
    for (int it = 0; it < 8; ++it) {
        int idx = it * 256 + tid;
        ob[idx] = tile[idx >> 6][idx & 63];
    }
}

// ---------------------------------------------------------------------------
extern "C" void kernel_launch(void* const* d_in, const int* in_sizes, int n_in,
                              void* d_out, int out_size) {
    const float* in;
    const float* w;
    if (in_sizes[0] == 64 * 512 * 512) { in = (const float*)d_in[0]; w = (const float*)d_in[1]; }
    else                               { in = (const float*)d_in[1]; w = (const float*)d_in[0]; }
    float* out = (float*)d_out;

    init_kernel<<<3, 256>>>();
    dim3 g1(16, 64);
    actmax_kernel<<<g1, 256>>>(in);
    scale_kernel<<<1, 576>>>(w, out);
    dim3 g3(16, 512);
    main_kernel<<<g3, 256>>>(in, out);
}